// round 4
// baseline (speedup 1.0000x reference)
#include <cuda_runtime.h>
#include <cuda_bf16.h>
#include <cstdint>

// ============================================================================
// out[t, k*512+c] = sum_b x[t, k*512+b] * blocks[k, b, c]
// 8 grouped GEMMs [16384,512]@[512,512], fp32 in/out.
//
// Harness compiles PTX for plain compute_103 (no 'a' suffix) -> tcgen05 is
// unavailable. Baseline-PTX tensor path: mma.sync.m16n8k16 bf16 with a
// 3xBF16 hi/lo split for fp32-grade accuracy (rel_err ~1e-5).
//
// R3 fix: ldmatrix addresses must be swizzled AFTER adding the k-step
// offset (SW(base+ko)), not SW(base)+ko which carries into the row field
// (wrong rows + 16B smem overrun -> illegal memory access).
// ============================================================================

#define NBLK   8
#define BLK    512
#define HIDDEN 4096
#define CTA_M  128
#define CTA_N  128
#define KC     32                  // K elems per chunk (64B bf16 rows)
#define NCH    (BLK / KC)          // 16
#define THREADS 256

// smem stage: A hi (8K) + A lo (8K) + B hi (8K) + B lo (8K) = 32 KB
#define AHI_OFF 0
#define ALO_OFF 8192
#define BHI_OFF 16384
#define BLO_OFF 24576
#define STAGE_BYTES 32768
#define NSTAGE 3
#define SMEM_TOTAL (NSTAGE * STAGE_BYTES)   // 96 KB

// XOR swizzle for 64B rows: bits[5:4] ^= row bits[2:1] (16B granularity)
#define SW(o) ((uint32_t)(o) ^ ((((uint32_t)(o)) >> 3) & 0x30))

// Pre-split B operand scratch: [k][c][b] bf16 (transposed, K contiguous)
__device__ __align__(128) __nv_bfloat16 g_Bhi[NBLK * BLK * BLK];
__device__ __align__(128) __nv_bfloat16 g_Blo[NBLK * BLK * BLK];

// ---------------------------------------------------------------- helpers
__device__ __forceinline__ uint32_t smem_to_u32(const void* p) {
    uint32_t a;
    asm("{ .reg .u64 t; cvta.to.shared.u64 t, %1; cvt.u32.u64 %0, t; }" : "=r"(a) : "l"(p));
    return a;
}

__device__ __forceinline__ void cp16(uint32_t dst, const void* src) {
    asm volatile("cp.async.cg.shared.global [%0], [%1], 16;" :: "r"(dst), "l"(src));
}
#define CP_COMMIT()  asm volatile("cp.async.commit_group;" ::: "memory")
#define CP_WAIT(N)   asm volatile("cp.async.wait_group %0;" :: "n"(N) : "memory")

__device__ __forceinline__ void ldm_x4(uint32_t* r, uint32_t addr) {
    asm volatile("ldmatrix.sync.aligned.m8n8.x4.shared.b16 {%0,%1,%2,%3}, [%4];"
                 : "=r"(r[0]), "=r"(r[1]), "=r"(r[2]), "=r"(r[3]) : "r"(addr));
}

__device__ __forceinline__ void mma16816(float* c, const uint32_t* a,
                                         uint32_t b0, uint32_t b1) {
    asm volatile(
        "mma.sync.aligned.m16n8k16.row.col.f32.bf16.bf16.f32 "
        "{%0,%1,%2,%3}, {%4,%5,%6,%7}, {%8,%9}, {%0,%1,%2,%3};"
        : "+f"(c[0]), "+f"(c[1]), "+f"(c[2]), "+f"(c[3])
        : "r"(a[0]), "r"(a[1]), "r"(a[2]), "r"(a[3]), "r"(b0), "r"(b1));
}

__device__ __forceinline__ uint32_t bf2_as_u32(__nv_bfloat162 v) {
    uint32_t u; __builtin_memcpy(&u, &v, 4); return u;
}

// 8 fp32 -> 8 bf16 hi (uint4) + 8 bf16 lo (uint4)
__device__ __forceinline__ void split8(const float4& p, const float4& q,
                                       uint4& hi, uint4& lo) {
    __nv_bfloat162 h;
    h = __floats2bfloat162_rn(p.x, p.y);
    hi.x = bf2_as_u32(h);
    lo.x = bf2_as_u32(__floats2bfloat162_rn(p.x - __low2float(h), p.y - __high2float(h)));
    h = __floats2bfloat162_rn(p.z, p.w);
    hi.y = bf2_as_u32(h);
    lo.y = bf2_as_u32(__floats2bfloat162_rn(p.z - __low2float(h), p.w - __high2float(h)));
    h = __floats2bfloat162_rn(q.x, q.y);
    hi.z = bf2_as_u32(h);
    lo.z = bf2_as_u32(__floats2bfloat162_rn(q.x - __low2float(h), q.y - __high2float(h)));
    h = __floats2bfloat162_rn(q.z, q.w);
    hi.w = bf2_as_u32(h);
    lo.w = bf2_as_u32(__floats2bfloat162_rn(q.z - __low2float(h), q.w - __high2float(h)));
}

// ---------------------------------------------------------------- prep kernel
// blocks[k][b][c] fp32 -> g_Bhi/g_Blo[k][c][b] bf16 (transpose + split)
__global__ void prep_B_kernel(const float* __restrict__ blocks) {
    __shared__ float t[32][33];
    int k = blockIdx.z;
    int c0 = blockIdx.x * 32;
    int b0 = blockIdx.y * 32;
    int tx = threadIdx.x, ty = threadIdx.y;
    #pragma unroll
    for (int j = ty; j < 32; j += 8)
        t[j][tx] = blocks[((size_t)k * BLK + b0 + j) * BLK + c0 + tx];
    __syncthreads();
    #pragma unroll
    for (int j = ty; j < 32; j += 8) {
        float v = t[tx][j];
        __nv_bfloat16 h = __float2bfloat16_rn(v);
        __nv_bfloat16 l = __float2bfloat16_rn(v - __bfloat162float(h));
        size_t o = ((size_t)k * BLK + c0 + j) * BLK + b0 + tx;
        g_Bhi[o] = h;
        g_Blo[o] = l;
    }
}

// ---------------------------------------------------------------- main kernel
__global__ void __launch_bounds__(THREADS, 2)
gemm_bd_kernel(const float* __restrict__ x, float* __restrict__ out, int mtiles) {
    extern __shared__ __align__(1024) char smem[];
    const uint32_t sb = smem_to_u32(smem);
    const int tid  = threadIdx.x;
    const int lane = tid & 31;
    const int wid  = tid >> 5;
    const int wm   = wid & 3;     // warp m-tile (32 rows)
    const int wn   = wid >> 2;    // warp n-tile (64 cols)

    const int bid   = blockIdx.x;
    const int ntile = bid & 3;
    const int tmp   = bid >> 2;
    const int mtile = tmp % mtiles;
    const int kblk  = tmp / mtiles;
    const int m0    = mtile * CTA_M;
    const int n0    = ntile * CTA_N;

    // ---- per-thread staging coords (A loads fp32 and splits; B cp.asyncs)
    const int r0 = tid >> 2;          // 0..63, second seg r0+64
    const int u  = tid & 3;           // 16B unit within 64B row
    const uint32_t st0 = SW(r0 * 64 + u * 16);
    const uint32_t st1 = SW((r0 + 64) * 64 + u * 16);

    const float4* x4 = (const float4*)x;
    const size_t xrow0 = (size_t)(m0 + r0) * (HIDDEN / 4);
    const size_t xrow1 = xrow0 + (size_t)64 * (HIDDEN / 4);
    const int kb4 = (kblk * BLK) / 4;   // + ch*8

    const __nv_bfloat16* bh0 = g_Bhi + ((size_t)(kblk * BLK + n0 + r0)) * BLK + u * 8;
    const __nv_bfloat16* bh1 = bh0 + (size_t)64 * BLK;
    const __nv_bfloat16* bl0 = g_Blo + ((size_t)(kblk * BLK + n0 + r0)) * BLK + u * 8;
    const __nv_bfloat16* bl1 = bl0 + (size_t)64 * BLK;

    // ---- ldmatrix base offsets (UNswizzled; swizzle applied after +ko)
    const int lrow = lane & 15;
    const int lkh  = lane >> 4;
    uint32_t a_base[2], b_base[4];
    #pragma unroll
    for (int mh = 0; mh < 2; mh++)
        a_base[mh] = (uint32_t)((wm * 32 + mh * 16 + lrow) * 64 + lkh * 16);
    #pragma unroll
    for (int g = 0; g < 4; g++)
        b_base[g] = (uint32_t)((wn * 64 + g * 16 + lrow) * 64 + lkh * 16);

    float acc[2][8][4];
    #pragma unroll
    for (int mh = 0; mh < 2; mh++)
        #pragma unroll
        for (int nj = 0; nj < 8; nj++)
            #pragma unroll
            for (int i = 0; i < 4; i++) acc[mh][nj][i] = 0.f;

    float4 av[4];

    // ---- A: LDG fp32 -> regs
    auto lda = [&](int ch) {
        int c4 = kb4 + ch * 8 + u * 2;
        av[0] = x4[xrow0 + c4];
        av[1] = x4[xrow0 + c4 + 1];
        av[2] = x4[xrow1 + c4];
        av[3] = x4[xrow1 + c4 + 1];
    };
    // ---- A: split regs -> smem hi/lo
    auto sta = [&](int slot) {
        char* s = smem + slot * STAGE_BYTES;
        uint4 hi, lo;
        split8(av[0], av[1], hi, lo);
        *(uint4*)(s + AHI_OFF + st0) = hi;
        *(uint4*)(s + ALO_OFF + st0) = lo;
        split8(av[2], av[3], hi, lo);
        *(uint4*)(s + AHI_OFF + st1) = hi;
        *(uint4*)(s + ALO_OFF + st1) = lo;
    };
    // ---- B: cp.async preconverted bf16 hi/lo
    auto ldb = [&](int ch, int slot) {
        uint32_t s = sb + slot * STAGE_BYTES;
        cp16(s + BHI_OFF + st0, bh0 + ch * KC);
        cp16(s + BHI_OFF + st1, bh1 + ch * KC);
        cp16(s + BLO_OFF + st0, bl0 + ch * KC);
        cp16(s + BLO_OFF + st1, bl1 + ch * KC);
    };
    // ---- compute one chunk: 2 k16-steps x (hi*hi + lo*hi + hi*lo)
    auto compute = [&](int slot) {
        uint32_t base = sb + slot * STAGE_BYTES;
        #pragma unroll
        for (int ks = 0; ks < 2; ks++) {
            uint32_t ko = (uint32_t)(ks * 32);
            uint32_t ah[2][4], al[2][4], bb[4][4];
            #pragma unroll
            for (int mh = 0; mh < 2; mh++) {
                ldm_x4(ah[mh], base + AHI_OFF + SW(a_base[mh] + ko));
                ldm_x4(al[mh], base + ALO_OFF + SW(a_base[mh] + ko));
            }
            #pragma unroll
            for (int g = 0; g < 4; g++)
                ldm_x4(bb[g], base + BHI_OFF + SW(b_base[g] + ko));
            #pragma unroll
            for (int mh = 0; mh < 2; mh++)
                #pragma unroll
                for (int nj = 0; nj < 8; nj++) {
                    uint32_t b0v = bb[nj >> 1][nj & 1];
                    uint32_t b1v = bb[nj >> 1][(nj & 1) + 2];
                    mma16816(acc[mh][nj], ah[mh], b0v, b1v);   // hi*hi
                    mma16816(acc[mh][nj], al[mh], b0v, b1v);   // lo*hi
                }
            #pragma unroll
            for (int g = 0; g < 4; g++)
                ldm_x4(bb[g], base + BLO_OFF + SW(b_base[g] + ko));
            #pragma unroll
            for (int mh = 0; mh < 2; mh++)
                #pragma unroll
                for (int nj = 0; nj < 8; nj++)
                    mma16816(acc[mh][nj], ah[mh],
                             bb[nj >> 1][nj & 1], bb[nj >> 1][(nj & 1) + 2]); // hi*lo
        }
    };

    // ---- prologue: fill stages 0,1
    ldb(0, 0); CP_COMMIT();
    ldb(1, 1); CP_COMMIT();
    lda(0); sta(0);
    lda(1); sta(1);
    CP_WAIT(1);           // chunk 0 B arrived
    __syncthreads();

    // ---- main loop: 3-stage ring, A reg-prefetch 2 ahead
    #pragma unroll 1
    for (int ch = 0; ch < NCH; ch++) {
        const bool pf = (ch + 2) < NCH;
        if (pf) lda(ch + 2);
        compute(ch % 3);
        __syncthreads();                 // slot (ch+2)%3 now free
        if (pf) {
            int slot = (ch + 2) % 3;
            sta(slot);
            ldb(ch + 2, slot); CP_COMMIT();
            CP_WAIT(1);                  // chunk ch+1 B arrived
        } else {
            CP_WAIT(0);
        }
        __syncthreads();
    }

    // ---- epilogue: direct STG (streaming, keep L2 for x/B)
    const int row_b = m0 + wm * 32 + (lane >> 2);
    const int col_b = kblk * BLK + n0 + wn * 64 + (lane & 3) * 2;
    #pragma unroll
    for (int mh = 0; mh < 2; mh++)
        #pragma unroll
        for (int nj = 0; nj < 8; nj++) {
            float* p = out + (size_t)(row_b + mh * 16) * HIDDEN + col_b + nj * 8;
            float2 v0 = make_float2(acc[mh][nj][0], acc[mh][nj][1]);
            float2 v1 = make_float2(acc[mh][nj][2], acc[mh][nj][3]);
            __stcs((float2*)p, v0);
            __stcs((float2*)(p + (size_t)8 * HIDDEN), v1);
        }
}

// ---------------------------------------------------------------- launch
extern "C" void kernel_launch(void* const* d_in, const int* in_sizes, int n_in,
                              void* d_out, int out_size) {
    const float* x      = (const float*)d_in[0];
    const float* blocks = (const float*)d_in[1];
    float* out          = (float*)d_out;

    int tokens = in_sizes[0] / HIDDEN;   // 16384
    int mtiles = tokens / CTA_M;         // 128

    cudaFuncSetAttribute(gemm_bd_kernel,
                         cudaFuncAttributeMaxDynamicSharedMemorySize, SMEM_TOTAL);

    // 1) transpose + bf16 hi/lo split of blocks (8 MB scratch, L2-resident)
    prep_B_kernel<<<dim3(BLK / 32, BLK / 32, NBLK), dim3(32, 8)>>>(blocks);

    // 2) grouped GEMM; the 4 N-tiles of each (mtile, kblk) are adjacent in
    //    the grid so their shared x tile hits L2 (4x read amplification
    //    collapses to ~1x DRAM).
    gemm_bd_kernel<<<mtiles * NBLK * 4, THREADS, SMEM_TOTAL>>>(x, out, mtiles);
}

// round 5
// speedup vs baseline: 1.1922x; 1.1922x over previous
#include <cuda_runtime.h>
#include <cuda_fp16.h>
#include <cstdint>

// ============================================================================
// out[t, k*512+c] = sum_b x[t, k*512+b] * blocks[k, b, c]
// 8 grouped GEMMs [16384,512]@[512,512], fp32 in/out.
//
// R5: single-pass FP16 mma.m16n8k16 (fp32 accum). Calibrated error model
// (R4: dropped-term eps -> rel_err ~= eps, norm-based) predicts rel_err
// ~3e-4 << 1e-3. Cuts tensor work 3x and smem traffic 2x vs the 3xBF16
// split. KC=64 (128B smem rows, SW128 swizzle), 3-stage cp.async ring.
// ============================================================================

#define NBLK   8
#define BLK    512
#define HIDDEN 4096
#define CTA_M  128
#define CTA_N  128
#define KC     64                  // K elems per chunk (128B fp16 rows)
#define NCH    (BLK / KC)          // 8
#define THREADS 256

// smem stage: A (16K) + B (16K) = 32 KB; 3 stages = 96 KB
#define A_OFF 0
#define B_OFF 16384
#define STAGE_BYTES 32768
#define SMEM_TOTAL (3 * STAGE_BYTES)

// SW128 swizzle for 128B rows: bits[6:4] ^= row bits[2:0]
#define SW(o) ((uint32_t)(o) ^ ((((uint32_t)(o)) >> 3) & 0x70))

// Pre-converted B operand scratch: [k][c][b] fp16 (transposed, K contiguous)
__device__ __align__(128) __half g_Bh[NBLK * BLK * BLK];

// ---------------------------------------------------------------- helpers
__device__ __forceinline__ uint32_t smem_to_u32(const void* p) {
    uint32_t a;
    asm("{ .reg .u64 t; cvta.to.shared.u64 t, %1; cvt.u32.u64 %0, t; }" : "=r"(a) : "l"(p));
    return a;
}

__device__ __forceinline__ void cp16(uint32_t dst, const void* src) {
    asm volatile("cp.async.cg.shared.global [%0], [%1], 16;" :: "r"(dst), "l"(src));
}
#define CP_COMMIT()  asm volatile("cp.async.commit_group;" ::: "memory")
#define CP_WAIT(N)   asm volatile("cp.async.wait_group %0;" :: "n"(N) : "memory")

__device__ __forceinline__ void ldm_x4(uint32_t* r, uint32_t addr) {
    asm volatile("ldmatrix.sync.aligned.m8n8.x4.shared.b16 {%0,%1,%2,%3}, [%4];"
                 : "=r"(r[0]), "=r"(r[1]), "=r"(r[2]), "=r"(r[3]) : "r"(addr));
}

__device__ __forceinline__ void mma16816(float* c, const uint32_t* a,
                                         uint32_t b0, uint32_t b1) {
    asm volatile(
        "mma.sync.aligned.m16n8k16.row.col.f32.f16.f16.f32 "
        "{%0,%1,%2,%3}, {%4,%5,%6,%7}, {%8,%9}, {%0,%1,%2,%3};"
        : "+f"(c[0]), "+f"(c[1]), "+f"(c[2]), "+f"(c[3])
        : "r"(a[0]), "r"(a[1]), "r"(a[2]), "r"(a[3]), "r"(b0), "r"(b1));
}

__device__ __forceinline__ uint32_t h2_as_u32(__half2 v) {
    uint32_t u; __builtin_memcpy(&u, &v, 4); return u;
}

// 8 fp32 -> 8 fp16 packed in a uint4
__device__ __forceinline__ uint4 cvt8(const float4& p, const float4& q) {
    uint4 r;
    r.x = h2_as_u32(__floats2half2_rn(p.x, p.y));
    r.y = h2_as_u32(__floats2half2_rn(p.z, p.w));
    r.z = h2_as_u32(__floats2half2_rn(q.x, q.y));
    r.w = h2_as_u32(__floats2half2_rn(q.z, q.w));
    return r;
}

// ---------------------------------------------------------------- prep kernel
// blocks[k][b][c] fp32 -> g_Bh[k][c][b] fp16 (transpose + convert)
__global__ void prep_B_kernel(const float* __restrict__ blocks) {
    __shared__ float t[32][33];
    int k = blockIdx.z;
    int c0 = blockIdx.x * 32;
    int b0 = blockIdx.y * 32;
    int tx = threadIdx.x, ty = threadIdx.y;
    #pragma unroll
    for (int j = ty; j < 32; j += 8)
        t[j][tx] = blocks[((size_t)k * BLK + b0 + j) * BLK + c0 + tx];
    __syncthreads();
    #pragma unroll
    for (int j = ty; j < 32; j += 8) {
        size_t o = ((size_t)k * BLK + c0 + j) * BLK + b0 + tx;
        g_Bh[o] = __float2half_rn(t[tx][j]);
    }
}

// ---------------------------------------------------------------- main kernel
__global__ void __launch_bounds__(THREADS, 2)
gemm_bd_kernel(const float* __restrict__ x, float* __restrict__ out, int mtiles) {
    extern __shared__ __align__(1024) char smem[];
    const uint32_t sb = smem_to_u32(smem);
    const int tid  = threadIdx.x;
    const int lane = tid & 31;
    const int wid  = tid >> 5;
    const int wm   = wid & 3;     // warp m-tile (32 rows)
    const int wn   = wid >> 2;    // warp n-tile (64 cols)

    const int bid   = blockIdx.x;
    const int ntile = bid & 3;
    const int tmp   = bid >> 2;
    const int mtile = tmp % mtiles;
    const int kblk  = tmp / mtiles;
    const int m0    = mtile * CTA_M;
    const int n0    = ntile * CTA_N;

    // ---- staging coords: warp lanes = consecutive rows (conflict-free STS)
    const int r0 = tid & 63;          // row 0..63, second seg +64
    const int v  = tid >> 6;          // 16B unit 0..3 (also covers v+4)
    const uint32_t st00 = SW(r0 * 128 + v * 16);
    const uint32_t st01 = SW(r0 * 128 + v * 16 + 64);
    const uint32_t st10 = SW((r0 + 64) * 128 + v * 16);
    const uint32_t st11 = SW((r0 + 64) * 128 + v * 16 + 64);

    const float4* x4 = (const float4*)x;
    const size_t xrow0 = (size_t)(m0 + r0) * (HIDDEN / 4);
    const size_t xrow1 = xrow0 + (size_t)64 * (HIDDEN / 4);
    const int kb4 = (kblk * BLK) / 4;   // float4 index; + ch*16

    const __half* bh0 = g_Bh + ((size_t)(kblk * BLK + n0 + r0)) * BLK + v * 8;
    const __half* bh1 = bh0 + (size_t)64 * BLK;

    // ---- ldmatrix base offsets (UNswizzled; swizzle applied after +ko)
    const int lrow = lane & 15;
    const int lkh  = lane >> 4;
    uint32_t a_base[2], b_base[4];
    #pragma unroll
    for (int mh = 0; mh < 2; mh++)
        a_base[mh] = (uint32_t)((wm * 32 + mh * 16 + lrow) * 128 + lkh * 16);
    #pragma unroll
    for (int g = 0; g < 4; g++)
        b_base[g] = (uint32_t)((wn * 64 + g * 16 + lrow) * 128 + lkh * 16);

    float acc[2][8][4];
    #pragma unroll
    for (int mh = 0; mh < 2; mh++)
        #pragma unroll
        for (int nj = 0; nj < 8; nj++)
            #pragma unroll
            for (int i = 0; i < 4; i++) acc[mh][nj][i] = 0.f;

    uint4 av[4];   // prefetched+converted A: (seg0 u=v, seg0 u=v+4, seg1 ...)

    // ---- A: LDG fp32 -> cvt fp16 -> regs
    auto lda = [&](int ch) {
        int c4 = kb4 + ch * 16 + v * 2;
        av[0] = cvt8(x4[xrow0 + c4],     x4[xrow0 + c4 + 1]);
        av[1] = cvt8(x4[xrow0 + c4 + 8], x4[xrow0 + c4 + 9]);
        av[2] = cvt8(x4[xrow1 + c4],     x4[xrow1 + c4 + 1]);
        av[3] = cvt8(x4[xrow1 + c4 + 8], x4[xrow1 + c4 + 9]);
    };
    // ---- A: regs -> smem
    auto sta = [&](int slot) {
        char* s = smem + slot * STAGE_BYTES + A_OFF;
        *(uint4*)(s + st00) = av[0];
        *(uint4*)(s + st01) = av[1];
        *(uint4*)(s + st10) = av[2];
        *(uint4*)(s + st11) = av[3];
    };
    // ---- B: cp.async preconverted fp16
    auto ldb = [&](int ch, int slot) {
        uint32_t s = sb + slot * STAGE_BYTES + B_OFF;
        cp16(s + st00, bh0 + ch * KC);
        cp16(s + st01, bh0 + ch * KC + 32);
        cp16(s + st10, bh1 + ch * KC);
        cp16(s + st11, bh1 + ch * KC + 32);
    };
    // ---- compute one chunk: 4 k16-steps, single pass
    auto compute = [&](int slot) {
        uint32_t base = sb + slot * STAGE_BYTES;
        #pragma unroll
        for (int ks = 0; ks < 4; ks++) {
            uint32_t ko = (uint32_t)(ks * 32);
            uint32_t ah[2][4], bb[4][4];
            #pragma unroll
            for (int mh = 0; mh < 2; mh++)
                ldm_x4(ah[mh], base + A_OFF + SW(a_base[mh] + ko));
            #pragma unroll
            for (int g = 0; g < 4; g++)
                ldm_x4(bb[g], base + B_OFF + SW(b_base[g] + ko));
            #pragma unroll
            for (int mh = 0; mh < 2; mh++)
                #pragma unroll
                for (int nj = 0; nj < 8; nj++)
                    mma16816(acc[mh][nj], ah[mh],
                             bb[nj >> 1][nj & 1], bb[nj >> 1][(nj & 1) + 2]);
        }
    };

    // ---- prologue: fill stages 0,1
    ldb(0, 0); CP_COMMIT();
    ldb(1, 1); CP_COMMIT();
    lda(0); sta(0);
    lda(1); sta(1);
    CP_WAIT(1);           // chunk 0 B arrived
    __syncthreads();

    // ---- main loop: 3-stage ring, A reg-prefetch 2 ahead
    #pragma unroll 1
    for (int ch = 0; ch < NCH; ch++) {
        const bool pf = (ch + 2) < NCH;
        if (pf) lda(ch + 2);
        compute(ch % 3);
        __syncthreads();                 // slot (ch+2)%3 now free
        if (pf) {
            int slot = (ch + 2) % 3;
            sta(slot);
            ldb(ch + 2, slot); CP_COMMIT();
            CP_WAIT(1);                  // chunk ch+1 B arrived
        } else {
            CP_WAIT(0);
        }
        __syncthreads();
    }

    // ---- epilogue: direct streaming STG
    const int row_b = m0 + wm * 32 + (lane >> 2);
    const int col_b = kblk * BLK + n0 + wn * 64 + (lane & 3) * 2;
    #pragma unroll
    for (int mh = 0; mh < 2; mh++)
        #pragma unroll
        for (int nj = 0; nj < 8; nj++) {
            float* p = out + (size_t)(row_b + mh * 16) * HIDDEN + col_b + nj * 8;
            float2 v0 = make_float2(acc[mh][nj][0], acc[mh][nj][1]);
            float2 v1 = make_float2(acc[mh][nj][2], acc[mh][nj][3]);
            __stcs((float2*)p, v0);
            __stcs((float2*)(p + (size_t)8 * HIDDEN), v1);
        }
}

// ---------------------------------------------------------------- launch
extern "C" void kernel_launch(void* const* d_in, const int* in_sizes, int n_in,
                              void* d_out, int out_size) {
    const float* x      = (const float*)d_in[0];
    const float* blocks = (const float*)d_in[1];
    float* out          = (float*)d_out;

    int tokens = in_sizes[0] / HIDDEN;   // 16384
    int mtiles = tokens / CTA_M;         // 128

    cudaFuncSetAttribute(gemm_bd_kernel,
                         cudaFuncAttributeMaxDynamicSharedMemorySize, SMEM_TOTAL);

    // 1) transpose + fp16 convert of blocks (4 MB scratch, L2-resident)
    prep_B_kernel<<<dim3(BLK / 32, BLK / 32, NBLK), dim3(32, 8)>>>(blocks);

    // 2) grouped GEMM; the 4 N-tiles of each (mtile, kblk) are adjacent in
    //    the grid so their shared x tile hits L2.
    gemm_bd_kernel<<<mtiles * NBLK * 4, THREADS, SMEM_TOTAL>>>(x, out, mtiles);
}

// round 6
// speedup vs baseline: 1.8582x; 1.5587x over previous
#include <cuda_runtime.h>
#include <cuda_fp16.h>
#include <cstdint>

// ============================================================================
// out[t, k*512+c] = sum_b x[t, k*512+b] * blocks[k, b, c]
// 8 grouped GEMMs [16384,512]@[512,512], fp32 in/out.
//
// R6: single-pass FP16 mma.m16n8k16 (rel_err ~3e-4, calibrated R4/R5).
// Fix vs R5: staging lane map was rows-per-lane -> every warp LDG/cp.async
// touched 32 cache lines (8x L1 wavefront amplification). Now 8 lanes cover
// one 128B row contiguously (u=tid&7, r=tid>>3): ideal 4 lines/warp-instr,
// conflict-free STS through the SW128 swizzle.
// ============================================================================

#define NBLK   8
#define BLK    512
#define HIDDEN 4096
#define CTA_M  128
#define CTA_N  128
#define KC     64                  // K elems per chunk (128B fp16 rows)
#define NCH    (BLK / KC)          // 8
#define THREADS 256

// smem stage: A (16K) + B (16K) = 32 KB; 3 stages = 96 KB
#define A_OFF 0
#define B_OFF 16384
#define STAGE_BYTES 32768
#define SMEM_TOTAL (3 * STAGE_BYTES)

// SW128 swizzle for 128B rows: bits[6:4] ^= row bits[2:0]
#define SW(o) ((uint32_t)(o) ^ ((((uint32_t)(o)) >> 3) & 0x70))

// Pre-converted B operand scratch: [k][c][b] fp16 (transposed, K contiguous)
__device__ __align__(128) __half g_Bh[NBLK * BLK * BLK];

// ---------------------------------------------------------------- helpers
__device__ __forceinline__ uint32_t smem_to_u32(const void* p) {
    uint32_t a;
    asm("{ .reg .u64 t; cvta.to.shared.u64 t, %1; cvt.u32.u64 %0, t; }" : "=r"(a) : "l"(p));
    return a;
}

__device__ __forceinline__ void cp16(uint32_t dst, const void* src) {
    asm volatile("cp.async.cg.shared.global [%0], [%1], 16;" :: "r"(dst), "l"(src));
}
#define CP_COMMIT()  asm volatile("cp.async.commit_group;" ::: "memory")
#define CP_WAIT(N)   asm volatile("cp.async.wait_group %0;" :: "n"(N) : "memory")

__device__ __forceinline__ void ldm_x4(uint32_t* r, uint32_t addr) {
    asm volatile("ldmatrix.sync.aligned.m8n8.x4.shared.b16 {%0,%1,%2,%3}, [%4];"
                 : "=r"(r[0]), "=r"(r[1]), "=r"(r[2]), "=r"(r[3]) : "r"(addr));
}

__device__ __forceinline__ void mma16816(float* c, const uint32_t* a,
                                         uint32_t b0, uint32_t b1) {
    asm volatile(
        "mma.sync.aligned.m16n8k16.row.col.f32.f16.f16.f32 "
        "{%0,%1,%2,%3}, {%4,%5,%6,%7}, {%8,%9}, {%0,%1,%2,%3};"
        : "+f"(c[0]), "+f"(c[1]), "+f"(c[2]), "+f"(c[3])
        : "r"(a[0]), "r"(a[1]), "r"(a[2]), "r"(a[3]), "r"(b0), "r"(b1));
}

__device__ __forceinline__ uint32_t h2_as_u32(__half2 v) {
    uint32_t u; __builtin_memcpy(&u, &v, 4); return u;
}

// 8 fp32 -> 8 fp16 packed in a uint4
__device__ __forceinline__ uint4 cvt8(const float4& p, const float4& q) {
    uint4 r;
    r.x = h2_as_u32(__floats2half2_rn(p.x, p.y));
    r.y = h2_as_u32(__floats2half2_rn(p.z, p.w));
    r.z = h2_as_u32(__floats2half2_rn(q.x, q.y));
    r.w = h2_as_u32(__floats2half2_rn(q.z, q.w));
    return r;
}

// ---------------------------------------------------------------- prep kernel
// blocks[k][b][c] fp32 -> g_Bh[k][c][b] fp16 (transpose + convert)
__global__ void prep_B_kernel(const float* __restrict__ blocks) {
    __shared__ float t[32][33];
    int k = blockIdx.z;
    int c0 = blockIdx.x * 32;
    int b0 = blockIdx.y * 32;
    int tx = threadIdx.x, ty = threadIdx.y;
    #pragma unroll
    for (int j = ty; j < 32; j += 8)
        t[j][tx] = blocks[((size_t)k * BLK + b0 + j) * BLK + c0 + tx];
    __syncthreads();
    #pragma unroll
    for (int j = ty; j < 32; j += 8) {
        size_t o = ((size_t)k * BLK + c0 + j) * BLK + b0 + tx;
        g_Bh[o] = __float2half_rn(t[tx][j]);
    }
}

// ---------------------------------------------------------------- main kernel
__global__ void __launch_bounds__(THREADS, 2)
gemm_bd_kernel(const float* __restrict__ x, float* __restrict__ out, int mtiles) {
    extern __shared__ __align__(1024) char smem[];
    const uint32_t sb = smem_to_u32(smem);
    const int tid  = threadIdx.x;
    const int lane = tid & 31;
    const int wid  = tid >> 5;
    const int wm   = wid & 3;     // warp m-tile (32 rows)
    const int wn   = wid >> 2;    // warp n-tile (64 cols)

    const int bid   = blockIdx.x;
    const int ntile = bid & 3;
    const int tmp   = bid >> 2;
    const int mtile = tmp % mtiles;
    const int kblk  = tmp / mtiles;
    const int m0    = mtile * CTA_M;
    const int n0    = ntile * CTA_N;

    // ---- staging coords: 8 lanes cover one 128B row (coalesced + no STS
    //      conflicts); 4 row-passes p cover 128 rows.
    const int u  = tid & 7;           // 16B unit within row
    const int rb = tid >> 3;          // row 0..31 (+32p)
    uint32_t stoff[4];
    #pragma unroll
    for (int p = 0; p < 4; p++)
        stoff[p] = SW((rb + 32 * p) * 128 + u * 16);

    const float4* x4 = (const float4*)x;
    size_t xrow[4];
    #pragma unroll
    for (int p = 0; p < 4; p++)
        xrow[p] = (size_t)(m0 + rb + 32 * p) * (HIDDEN / 4);
    const int kb4 = (kblk * BLK) / 4;   // float4 index; + ch*16 + u*2

    const __half* bptr[4];
    #pragma unroll
    for (int p = 0; p < 4; p++)
        bptr[p] = g_Bh + ((size_t)(kblk * BLK + n0 + rb + 32 * p)) * BLK + u * 8;

    // ---- ldmatrix base offsets (UNswizzled; swizzle applied after +ko)
    const int lrow = lane & 15;
    const int lkh  = lane >> 4;
    uint32_t a_base[2], b_base[4];
    #pragma unroll
    for (int mh = 0; mh < 2; mh++)
        a_base[mh] = (uint32_t)((wm * 32 + mh * 16 + lrow) * 128 + lkh * 16);
    #pragma unroll
    for (int g = 0; g < 4; g++)
        b_base[g] = (uint32_t)((wn * 64 + g * 16 + lrow) * 128 + lkh * 16);

    float acc[2][8][4];
    #pragma unroll
    for (int mh = 0; mh < 2; mh++)
        #pragma unroll
        for (int nj = 0; nj < 8; nj++)
            #pragma unroll
            for (int i = 0; i < 4; i++) acc[mh][nj][i] = 0.f;

    uint4 av[4];   // prefetched+converted A, one uint4 per row-pass

    // ---- A: LDG fp32 (coalesced) -> cvt fp16 -> regs
    auto lda = [&](int ch) {
        int c4 = kb4 + ch * 16 + u * 2;
        #pragma unroll
        for (int p = 0; p < 4; p++)
            av[p] = cvt8(x4[xrow[p] + c4], x4[xrow[p] + c4 + 1]);
    };
    // ---- A: regs -> smem (conflict-free)
    auto sta = [&](int slot) {
        char* s = smem + slot * STAGE_BYTES + A_OFF;
        #pragma unroll
        for (int p = 0; p < 4; p++)
            *(uint4*)(s + stoff[p]) = av[p];
    };
    // ---- B: cp.async preconverted fp16 (coalesced)
    auto ldb = [&](int ch, int slot) {
        uint32_t s = sb + slot * STAGE_BYTES + B_OFF;
        #pragma unroll
        for (int p = 0; p < 4; p++)
            cp16(s + stoff[p], bptr[p] + ch * KC);
    };
    // ---- compute one chunk: 4 k16-steps, single pass
    auto compute = [&](int slot) {
        uint32_t base = sb + slot * STAGE_BYTES;
        #pragma unroll
        for (int ks = 0; ks < 4; ks++) {
            uint32_t ko = (uint32_t)(ks * 32);
            uint32_t ah[2][4], bb[4][4];
            #pragma unroll
            for (int mh = 0; mh < 2; mh++)
                ldm_x4(ah[mh], base + A_OFF + SW(a_base[mh] + ko));
            #pragma unroll
            for (int g = 0; g < 4; g++)
                ldm_x4(bb[g], base + B_OFF + SW(b_base[g] + ko));
            #pragma unroll
            for (int mh = 0; mh < 2; mh++)
                #pragma unroll
                for (int nj = 0; nj < 8; nj++)
                    mma16816(acc[mh][nj], ah[mh],
                             bb[nj >> 1][nj & 1], bb[nj >> 1][(nj & 1) + 2]);
        }
    };

    // ---- prologue: fill stages 0,1
    ldb(0, 0); CP_COMMIT();
    ldb(1, 1); CP_COMMIT();
    lda(0); sta(0);
    lda(1); sta(1);
    CP_WAIT(1);           // chunk 0 B arrived
    __syncthreads();

    // ---- main loop: 3-stage ring, A reg-prefetch 2 ahead
    #pragma unroll 1
    for (int ch = 0; ch < NCH; ch++) {
        const bool pf = (ch + 2) < NCH;
        if (pf) lda(ch + 2);
        compute(ch % 3);
        __syncthreads();                 // slot (ch+2)%3 now free
        if (pf) {
            int slot = (ch + 2) % 3;
            sta(slot);
            ldb(ch + 2, slot); CP_COMMIT();
            CP_WAIT(1);                  // chunk ch+1 B arrived
        } else {
            CP_WAIT(0);
        }
        __syncthreads();
    }

    // ---- epilogue: direct streaming STG
    const int row_b = m0 + wm * 32 + (lane >> 2);
    const int col_b = kblk * BLK + n0 + wn * 64 + (lane & 3) * 2;
    #pragma unroll
    for (int mh = 0; mh < 2; mh++)
        #pragma unroll
        for (int nj = 0; nj < 8; nj++) {
            float* p = out + (size_t)(row_b + mh * 16) * HIDDEN + col_b + nj * 8;
            float2 v0 = make_float2(acc[mh][nj][0], acc[mh][nj][1]);
            float2 v1 = make_float2(acc[mh][nj][2], acc[mh][nj][3]);
            __stcs((float2*)p, v0);
            __stcs((float2*)(p + (size_t)8 * HIDDEN), v1);
        }
}

// ---------------------------------------------------------------- launch
extern "C" void kernel_launch(void* const* d_in, const int* in_sizes, int n_in,
                              void* d_out, int out_size) {
    const float* x      = (const float*)d_in[0];
    const float* blocks = (const float*)d_in[1];
    float* out          = (float*)d_out;

    int tokens = in_sizes[0] / HIDDEN;   // 16384
    int mtiles = tokens / CTA_M;         // 128

    cudaFuncSetAttribute(gemm_bd_kernel,
                         cudaFuncAttributeMaxDynamicSharedMemorySize, SMEM_TOTAL);

    // 1) transpose + fp16 convert of blocks (4 MB scratch, L2-resident)
    prep_B_kernel<<<dim3(BLK / 32, BLK / 32, NBLK), dim3(32, 8)>>>(blocks);

    // 2) grouped GEMM; the 4 N-tiles of each (mtile, kblk) are adjacent in
    //    the grid so their shared x tile hits L2.
    gemm_bd_kernel<<<mtiles * NBLK * 4, THREADS, SMEM_TOTAL>>>(x, out, mtiles);
}